// round 12
// baseline (speedup 1.0000x reference)
#include <cuda_runtime.h>
#include <cstdint>

// ---------------------------------------------------------------------------
// GAT 2-layer: N=50000, E=400000 (+N self loops), HEADS=4
// tf32 GEMM (float2-packed smem, register-staged B — R9 version) + fused
// att-coef epilogue, single-pass softmax aggregation, single-kernel scan.
// ---------------------------------------------------------------------------

#define NMAX   50000
#define EMAX   400000
#define TOTMAX (NMAX + EMAX)
#define FDIM   256

__device__ __align__(16) float g_h1[NMAX * FDIM];
__device__ __align__(16) float g_act[NMAX * FDIM];
__device__ __align__(16) float g_h2[NMAX * FDIM];
__device__ __align__(16) float g_asrc[NMAX * 4];
__device__ __align__(16) float g_adst[NMAX * 4];
__device__ int   g_deg[NMAX];
__device__ int   g_off[NMAX + 1];
__device__ int   g_cur[NMAX];
__device__ int   g_csrc[TOTMAX];
__device__ int   g_is64;

// ---------------------------------------------------------------------------
__device__ __forceinline__ int edge_at(const void* ei, int E, int which, int i, int is64)
{
    if (is64) {
        const long long* p = (const long long*)ei;
        return (int)p[(size_t)which * E + i];
    } else {
        const int* p = (const int*)ei;
        return p[(size_t)which * E + i];
    }
}

// detect int64-vs-int32 edge dtype AND init degree array (fused)
__global__ void k_init(const int* ei32, int E, int N)
{
    int i = blockIdx.x * blockDim.x + threadIdx.x;
    if (i < N) g_deg[i] = 1;  // self loop
    if (i == 0) {
        int allz = 1;
        int limit = (E < 64) ? E : 64;
        for (int k = 0; k < limit; k++)
            if (ei32[2 * k + 1] != 0) { allz = 0; break; }
        g_is64 = allz;
    }
}

// ---------------------------------------------------------------------------
// TF32 GEMM, 128x128 tile, BK=16 double-buffered, k-pair-packed smem,
// register-staged A and B (R9-proven version), fused att-coef epilogue.
// ---------------------------------------------------------------------------
__device__ __forceinline__ uint32_t f2tf32(float f)
{
    uint32_t r;
    asm("cvt.rna.tf32.f32 %0, %1;" : "=r"(r) : "f"(f));
    return r;
}

__device__ __forceinline__ void mma_tf32(float* d, const uint32_t* a, const uint32_t* b)
{
    asm volatile(
        "mma.sync.aligned.m16n8k8.row.col.f32.tf32.tf32.f32 "
        "{%0,%1,%2,%3}, {%4,%5,%6,%7}, {%8,%9}, {%0,%1,%2,%3};"
        : "+f"(d[0]), "+f"(d[1]), "+f"(d[2]), "+f"(d[3])
        : "r"(a[0]), "r"(a[1]), "r"(a[2]), "r"(a[3]), "r"(b[0]), "r"(b[1]));
}

#define AS2_STRIDE 12    // float2 units
#define BS2_STRIDE 132   // float2 units

__global__ void __launch_bounds__(256, 2)
k_gemm_tf32(const float* __restrict__ A, const float* __restrict__ B,
            float* __restrict__ C, int M,
            const float* __restrict__ atts, const float* __restrict__ attd)
{
    __shared__ float2 As2[2][128][AS2_STRIDE];
    __shared__ float2 Bs2[2][8][BS2_STRIDE];
    __shared__ float sPS[128][2];
    __shared__ float sPD[128][2];

    int tid  = threadIdx.x;
    int lane = tid & 31, wid = tid >> 5;
    int wm = wid & 1, wn = wid >> 1;
    int g = lane >> 2, t = lane & 3;

    int rowBase = blockIdx.x * 128;
    int colBase = blockIdx.y * 128;

    int arow = tid >> 1;
    int akc  = tid & 1;
    int brg  = tid >> 6;              // 0..3
    int bcol = (tid & 63) * 2;        // 0..126

    const float* Aptr = A + (size_t)(rowBase + arow) * 256 + akc * 8;
    const float* Bptr = B + (size_t)brg * 256 + colBase + bcol;
    bool aValid = (rowBase + arow) < M;

    const float4 z4 = make_float4(0.f, 0.f, 0.f, 0.f);
    float4 av0, av1;
    float2 bv0, bv1, bv2, bv3;

    av0 = aValid ? *(const float4*)(Aptr)     : z4;
    av1 = aValid ? *(const float4*)(Aptr + 4) : z4;
    bv0 = *(const float2*)(Bptr);
    bv1 = *(const float2*)(Bptr + 4 * 256);
    bv2 = *(const float2*)(Bptr + 8 * 256);
    bv3 = *(const float2*)(Bptr + 12 * 256);

    {
        float v[8] = {av0.x, av0.y, av0.z, av0.w, av1.x, av1.y, av1.z, av1.w};
        #pragma unroll
        for (int i = 0; i < 4; i++) {
            float2 p;
            *(uint32_t*)&p.x = f2tf32(v[i]);
            *(uint32_t*)&p.y = f2tf32(v[i + 4]);
            As2[0][arow][akc * 4 + i] = p;
        }
        float2 p0, p1, p2, p3;
        *(uint32_t*)&p0.x = f2tf32(bv0.x); *(uint32_t*)&p0.y = f2tf32(bv1.x);
        *(uint32_t*)&p1.x = f2tf32(bv0.y); *(uint32_t*)&p1.y = f2tf32(bv1.y);
        *(uint32_t*)&p2.x = f2tf32(bv2.x); *(uint32_t*)&p2.y = f2tf32(bv3.x);
        *(uint32_t*)&p3.x = f2tf32(bv2.y); *(uint32_t*)&p3.y = f2tf32(bv3.y);
        Bs2[0][brg][bcol]         = p0;
        Bs2[0][brg][bcol + 1]     = p1;
        Bs2[0][brg + 4][bcol]     = p2;
        Bs2[0][brg + 4][bcol + 1] = p3;
    }

    if (tid < 128) {
        sPS[tid][0] = 0.f; sPS[tid][1] = 0.f;
        sPD[tid][0] = 0.f; sPD[tid][1] = 0.f;
    }
    __syncthreads();

    float acc[4][4][4];
    #pragma unroll
    for (int i = 0; i < 4; i++)
        #pragma unroll
        for (int j = 0; j < 4; j++)
            #pragma unroll
            for (int k = 0; k < 4; k++) acc[i][j][k] = 0.f;

    #pragma unroll 1
    for (int kt = 0; kt < 16; kt++) {
        int cur = kt & 1;

        if (kt < 15) {
            const float* Ap = Aptr + (kt + 1) * 16;
            const float* Bp = Bptr + (size_t)(kt + 1) * 16 * 256;
            av0 = aValid ? *(const float4*)(Ap)     : z4;
            av1 = aValid ? *(const float4*)(Ap + 4) : z4;
            bv0 = *(const float2*)(Bp);
            bv1 = *(const float2*)(Bp + 4 * 256);
            bv2 = *(const float2*)(Bp + 8 * 256);
            bv3 = *(const float2*)(Bp + 12 * 256);
        }

        #pragma unroll
        for (int kc = 0; kc < 2; kc++) {
            int kp = kc * 4 + t;
            uint32_t af[4][4], bf[4][2];
            #pragma unroll
            for (int mt = 0; mt < 4; mt++) {
                int m0 = wm * 64 + mt * 16 + g;
                float2 pa0 = As2[cur][m0][kp];
                float2 pa1 = As2[cur][m0 + 8][kp];
                af[mt][0] = *(uint32_t*)&pa0.x;
                af[mt][1] = *(uint32_t*)&pa1.x;
                af[mt][2] = *(uint32_t*)&pa0.y;
                af[mt][3] = *(uint32_t*)&pa1.y;
            }
            #pragma unroll
            for (int nt = 0; nt < 4; nt++) {
                int n0 = wn * 32 + nt * 8 + g;
                float2 pb = Bs2[cur][kp][n0];
                bf[nt][0] = *(uint32_t*)&pb.x;
                bf[nt][1] = *(uint32_t*)&pb.y;
            }
            #pragma unroll
            for (int mt = 0; mt < 4; mt++)
                #pragma unroll
                for (int nt = 0; nt < 4; nt++)
                    mma_tf32(acc[mt][nt], af[mt], bf[nt]);
        }

        if (kt < 15) {
            int nxt = cur ^ 1;
            float v[8] = {av0.x, av0.y, av0.z, av0.w, av1.x, av1.y, av1.z, av1.w};
            #pragma unroll
            for (int i = 0; i < 4; i++) {
                float2 p;
                *(uint32_t*)&p.x = f2tf32(v[i]);
                *(uint32_t*)&p.y = f2tf32(v[i + 4]);
                As2[nxt][arow][akc * 4 + i] = p;
            }
            float2 p0, p1, p2, p3;
            *(uint32_t*)&p0.x = f2tf32(bv0.x); *(uint32_t*)&p0.y = f2tf32(bv1.x);
            *(uint32_t*)&p1.x = f2tf32(bv0.y); *(uint32_t*)&p1.y = f2tf32(bv1.y);
            *(uint32_t*)&p2.x = f2tf32(bv2.x); *(uint32_t*)&p2.y = f2tf32(bv3.x);
            *(uint32_t*)&p3.x = f2tf32(bv2.y); *(uint32_t*)&p3.y = f2tf32(bv3.y);
            Bs2[nxt][brg][bcol]         = p0;
            Bs2[nxt][brg][bcol + 1]     = p1;
            Bs2[nxt][brg + 4][bcol]     = p2;
            Bs2[nxt][brg + 4][bcol + 1] = p3;
            __syncthreads();
        }
    }

    // ---- store C ----
    #pragma unroll
    for (int mt = 0; mt < 4; mt++) {
        int r0 = rowBase + wm * 64 + mt * 16 + g;
        int r1 = r0 + 8;
        #pragma unroll
        for (int nt = 0; nt < 4; nt++) {
            int c = colBase + wn * 32 + nt * 8 + 2 * t;
            if (r0 < M)
                *(float2*)(&C[(size_t)r0 * 256 + c]) = make_float2(acc[mt][nt][0], acc[mt][nt][1]);
            if (r1 < M)
                *(float2*)(&C[(size_t)r1 * 256 + c]) = make_float2(acc[mt][nt][2], acc[mt][nt][3]);
        }
    }

    // ---- fused attention-coefficient epilogue ----
    int hl = wn >> 1;
    float ps[4][2], pd[4][2];
    #pragma unroll
    for (int mt = 0; mt < 4; mt++) {
        ps[mt][0] = 0.f; ps[mt][1] = 0.f;
        pd[mt][0] = 0.f; pd[mt][1] = 0.f;
    }
    #pragma unroll
    for (int nt = 0; nt < 4; nt++) {
        int c = colBase + wn * 32 + nt * 8 + 2 * t;
        float as0 = atts[c], as1 = atts[c + 1];
        float ad0 = attd[c], ad1 = attd[c + 1];
        #pragma unroll
        for (int mt = 0; mt < 4; mt++) {
            ps[mt][0] += acc[mt][nt][0] * as0 + acc[mt][nt][1] * as1;
            ps[mt][1] += acc[mt][nt][2] * as0 + acc[mt][nt][3] * as1;
            pd[mt][0] += acc[mt][nt][0] * ad0 + acc[mt][nt][1] * ad1;
            pd[mt][1] += acc[mt][nt][2] * ad0 + acc[mt][nt][3] * ad1;
        }
    }
    #pragma unroll
    for (int o = 1; o <= 2; o <<= 1) {
        #pragma unroll
        for (int mt = 0; mt < 4; mt++) {
            ps[mt][0] += __shfl_xor_sync(0xffffffffu, ps[mt][0], o);
            ps[mt][1] += __shfl_xor_sync(0xffffffffu, ps[mt][1], o);
            pd[mt][0] += __shfl_xor_sync(0xffffffffu, pd[mt][0], o);
            pd[mt][1] += __shfl_xor_sync(0xffffffffu, pd[mt][1], o);
        }
    }
    if (t == 0) {
        #pragma unroll
        for (int mt = 0; mt < 4; mt++) {
            int rl0 = wm * 64 + mt * 16 + g;
            atomicAdd(&sPS[rl0][hl],     ps[mt][0]);
            atomicAdd(&sPS[rl0 + 8][hl], ps[mt][1]);
            atomicAdd(&sPD[rl0][hl],     pd[mt][0]);
            atomicAdd(&sPD[rl0 + 8][hl], pd[mt][1]);
        }
    }
    __syncthreads();
    if (tid < 128) {
        int r = rowBase + tid;
        if (r < M) {
            int hb = blockIdx.y * 2;
            g_asrc[r * 4 + hb]     = sPS[tid][0];
            g_asrc[r * 4 + hb + 1] = sPS[tid][1];
            g_adst[r * 4 + hb]     = sPD[tid][0];
            g_adst[r * 4 + hb + 1] = sPD[tid][1];
        }
    }
}

// --------------------------- CSR construction ------------------------------
__global__ void k_hist(const void* __restrict__ ei, int E)
{
    int i = blockIdx.x * blockDim.x + threadIdx.x;
    if (i < E) {
        int d = edge_at(ei, E, 1, i, g_is64);
        atomicAdd(&g_deg[d], 1);
    }
}

// Single-block full exclusive scan of g_deg[0..n) -> g_off/g_cur; g_off[n]=tot.
__global__ void k_scanall(int n, int tot)
{
    __shared__ int wsum[32];
    int tid = threadIdx.x;
    int lane = tid & 31, wid = tid >> 5;
    int CH = (n + 1023) >> 10;
    int lo = tid * CH;
    int hi = lo + CH; if (hi > n) hi = n;

    int sum = 0;
    for (int i = lo; i < hi; i++) sum += g_deg[i];

    int s = sum;
    #pragma unroll
    for (int o = 1; o < 32; o <<= 1) {
        int u = __shfl_up_sync(0xffffffffu, s, o);
        if (lane >= o) s += u;
    }
    if (lane == 31) wsum[wid] = s;
    __syncthreads();
    if (wid == 0) {
        int w = wsum[lane];
        int wi = w;
        #pragma unroll
        for (int o = 1; o < 32; o <<= 1) {
            int u = __shfl_up_sync(0xffffffffu, wi, o);
            if (lane >= o) wi += u;
        }
        wsum[lane] = wi - w;
    }
    __syncthreads();

    int run = (s - sum) + wsum[wid];
    for (int i = lo; i < hi; i++) {
        g_off[i] = run;
        g_cur[i] = run;
        run += g_deg[i];
    }
    if (tid == 0) g_off[n] = tot;
}

__global__ void k_scatter(const void* __restrict__ ei, int E, int N)
{
    int i = blockIdx.x * blockDim.x + threadIdx.x;
    int tot = E + N;
    if (i >= tot) return;
    int s, d;
    if (i < E) {
        int is64 = g_is64;
        s = edge_at(ei, E, 0, i, is64);
        d = edge_at(ei, E, 1, i, is64);
    } else {
        s = d = i - E;
    }
    int pos = atomicAdd(&g_cur[d], 1);
    g_csrc[pos] = s;
}

// ---------------------------------------------------------------------------
// Aggregation: one warp per node, single pass, no max subtraction.
// ---------------------------------------------------------------------------
__global__ void k_aggregate3(const float* __restrict__ feat,
                             const float* __restrict__ bias,
                             float* __restrict__ outp, int N, int mode)
{
    int n = (blockIdx.x * blockDim.x + threadIdx.x) >> 5;
    int lane = threadIdx.x & 31;
    if (n >= N) return;

    int s0 = g_off[n], s1 = g_off[n + 1];
    int myh = lane >> 3;
    float myAd = g_adst[n * 4 + myh];
    int coff = lane * 8;

    float denom = 0.f;
    float4 acc0 = make_float4(0.f, 0.f, 0.f, 0.f);
    float4 acc1 = make_float4(0.f, 0.f, 0.f, 0.f);

    for (int j = s0; j < s1; j++) {
        int src = g_csrc[j];
        float e = g_asrc[src * 4 + myh] + myAd;
        e = (e < 0.f) ? 0.2f * e : e;
        float wt = __expf(e);
        denom += wt;
        const float4* hp = (const float4*)(feat + (size_t)src * FDIM + coff);
        float4 v0 = hp[0], v1 = hp[1];
        acc0.x = fmaf(wt, v0.x, acc0.x); acc0.y = fmaf(wt, v0.y, acc0.y);
        acc0.z = fmaf(wt, v0.z, acc0.z); acc0.w = fmaf(wt, v0.w, acc0.w);
        acc1.x = fmaf(wt, v1.x, acc1.x); acc1.y = fmaf(wt, v1.y, acc1.y);
        acc1.z = fmaf(wt, v1.z, acc1.z); acc1.w = fmaf(wt, v1.w, acc1.w);
    }
    float inv = 1.f / denom;
    acc0.x *= inv; acc0.y *= inv; acc0.z *= inv; acc0.w *= inv;
    acc1.x *= inv; acc1.y *= inv; acc1.z *= inv; acc1.w *= inv;

    if (mode == 1) {
        const float4* bp = (const float4*)(bias + coff);
        float4 b0 = bp[0], b1 = bp[1];
        float o0[8] = {acc0.x + b0.x, acc0.y + b0.y, acc0.z + b0.z, acc0.w + b0.w,
                       acc1.x + b1.x, acc1.y + b1.y, acc1.z + b1.z, acc1.w + b1.w};
        #pragma unroll
        for (int i = 0; i < 8; i++) o0[i] = (o0[i] > 0.f) ? o0[i] : expm1f(o0[i]);
        float* op = outp + (size_t)n * FDIM + coff;
        *(float4*)(op)     = make_float4(o0[0], o0[1], o0[2], o0[3]);
        *(float4*)(op + 4) = make_float4(o0[4], o0[5], o0[6], o0[7]);
    } else {
        float v[8] = {acc0.x, acc0.y, acc0.z, acc0.w, acc1.x, acc1.y, acc1.z, acc1.w};
        #pragma unroll
        for (int o = 8; o <= 16; o <<= 1)
            #pragma unroll
            for (int i = 0; i < 8; i++)
                v[i] += __shfl_xor_sync(0xffffffffu, v[i], o);
        if (lane < 8) {
            int c = lane * 8;
            const float4* bp = (const float4*)(bias + c);
            float4 b0 = bp[0], b1 = bp[1];
            float* op = outp + (size_t)n * 64 + c;
            *(float4*)(op) = make_float4(0.25f * v[0] + b0.x, 0.25f * v[1] + b0.y,
                                         0.25f * v[2] + b0.z, 0.25f * v[3] + b0.w);
            *(float4*)(op + 4) = make_float4(0.25f * v[4] + b1.x, 0.25f * v[5] + b1.y,
                                             0.25f * v[6] + b1.z, 0.25f * v[7] + b1.w);
        }
    }
}

// ---------------------------------------------------------------------------
extern "C" void kernel_launch(void* const* d_in, const int* in_sizes, int n_in,
                              void* d_out, int out_size)
{
    const float* x     = (const float*)d_in[0];
    const void*  ei    = d_in[1];
    const float* W1    = (const float*)d_in[2];
    const float* atts1 = (const float*)d_in[3];
    const float* attd1 = (const float*)d_in[4];
    const float* bias1 = (const float*)d_in[5];
    const float* W2    = (const float*)d_in[6];
    const float* atts2 = (const float*)d_in[7];
    const float* attd2 = (const float*)d_in[8];
    const float* bias2 = (const float*)d_in[9];

    int N = in_sizes[0] / FDIM;      // 50000
    int E = in_sizes[1] / 2;         // 400000
    int tot = E + N;

    void *ph1, *pact, *ph2;
    cudaGetSymbolAddress(&ph1, g_h1);
    cudaGetSymbolAddress(&pact, g_act);
    cudaGetSymbolAddress(&ph2, g_h2);
    float* h1  = (float*)ph1;
    float* act = (float*)pact;
    float* h2  = (float*)ph2;
    float* z   = (float*)d_out;

    dim3 gemmGrid((N + 127) / 128, 2);
    int aggBlocks = (N * 32 + 255) / 256;

    // --- Layer-1 GEMM first (independent of CSR) ---
    k_gemm_tf32<<<gemmGrid, 256>>>(x, W1, h1, N, atts1, attd1);

    // --- CSR build ---
    k_init<<<(N + 255) / 256, 256>>>((const int*)ei, E, N);
    k_hist<<<(E + 255) / 256, 256>>>(ei, E);
    k_scanall<<<1, 1024>>>(N, tot);
    k_scatter<<<(tot + 255) / 256, 256>>>(ei, E, N);

    // --- Layer 1 aggregate ---
    k_aggregate3<<<aggBlocks, 256>>>(h1, bias1, act, N, 1);

    // --- Layer 2 ---
    k_gemm_tf32<<<gemmGrid, 256>>>(act, W2, h2, N, atts2, attd2);
    k_aggregate3<<<aggBlocks, 256>>>(h2, bias2, z, N, 2);
}

// round 13
// speedup vs baseline: 1.2748x; 1.2748x over previous
#include <cuda_runtime.h>
#include <cstdint>

// ---------------------------------------------------------------------------
// GAT 2-layer: N=50000, E=400000 (+N self loops), HEADS=4
// tf32 GEMM (float2-packed smem, register-staged B — R9 version) + fused
// att-coef epilogue, single-pass softmax aggregation, R9 3-kernel scan.
// ---------------------------------------------------------------------------

#define NMAX   50000
#define EMAX   400000
#define TOTMAX (NMAX + EMAX)
#define FDIM   256

__device__ __align__(16) float g_h1[NMAX * FDIM];
__device__ __align__(16) float g_act[NMAX * FDIM];
__device__ __align__(16) float g_h2[NMAX * FDIM];
__device__ __align__(16) float g_asrc[NMAX * 4];
__device__ __align__(16) float g_adst[NMAX * 4];
__device__ int   g_deg[NMAX];
__device__ int   g_off[NMAX + 1];
__device__ int   g_cur[NMAX];
__device__ int   g_bsum[64];
__device__ int   g_csrc[TOTMAX];
__device__ int   g_is64;

// ---------------------------------------------------------------------------
__device__ __forceinline__ int edge_at(const void* ei, int E, int which, int i, int is64)
{
    if (is64) {
        const long long* p = (const long long*)ei;
        return (int)p[(size_t)which * E + i];
    } else {
        const int* p = (const int*)ei;
        return p[(size_t)which * E + i];
    }
}

// detect int64-vs-int32 edge dtype AND init degree array (fused)
__global__ void k_init(const int* ei32, int E, int N)
{
    int i = blockIdx.x * blockDim.x + threadIdx.x;
    if (i < N) g_deg[i] = 1;  // self loop
    if (i == 0) {
        int allz = 1;
        int limit = (E < 64) ? E : 64;
        for (int k = 0; k < limit; k++)
            if (ei32[2 * k + 1] != 0) { allz = 0; break; }
        g_is64 = allz;
    }
}

// ---------------------------------------------------------------------------
// TF32 GEMM, 128x128 tile, BK=16 double-buffered, k-pair-packed smem,
// register-staged A and B (R9-proven version), fused att-coef epilogue.
// ---------------------------------------------------------------------------
__device__ __forceinline__ uint32_t f2tf32(float f)
{
    uint32_t r;
    asm("cvt.rna.tf32.f32 %0, %1;" : "=r"(r) : "f"(f));
    return r;
}

__device__ __forceinline__ void mma_tf32(float* d, const uint32_t* a, const uint32_t* b)
{
    asm volatile(
        "mma.sync.aligned.m16n8k8.row.col.f32.tf32.tf32.f32 "
        "{%0,%1,%2,%3}, {%4,%5,%6,%7}, {%8,%9}, {%0,%1,%2,%3};"
        : "+f"(d[0]), "+f"(d[1]), "+f"(d[2]), "+f"(d[3])
        : "r"(a[0]), "r"(a[1]), "r"(a[2]), "r"(a[3]), "r"(b[0]), "r"(b[1]));
}

#define AS2_STRIDE 12    // float2 units
#define BS2_STRIDE 132   // float2 units

__global__ void __launch_bounds__(256, 2)
k_gemm_tf32(const float* __restrict__ A, const float* __restrict__ B,
            float* __restrict__ C, int M,
            const float* __restrict__ atts, const float* __restrict__ attd)
{
    __shared__ float2 As2[2][128][AS2_STRIDE];
    __shared__ float2 Bs2[2][8][BS2_STRIDE];
    __shared__ float sPS[128][2];
    __shared__ float sPD[128][2];

    int tid  = threadIdx.x;
    int lane = tid & 31, wid = tid >> 5;
    int wm = wid & 1, wn = wid >> 1;
    int g = lane >> 2, t = lane & 3;

    int rowBase = blockIdx.x * 128;
    int colBase = blockIdx.y * 128;

    int arow = tid >> 1;
    int akc  = tid & 1;
    int brg  = tid >> 6;              // 0..3
    int bcol = (tid & 63) * 2;        // 0..126

    const float* Aptr = A + (size_t)(rowBase + arow) * 256 + akc * 8;
    const float* Bptr = B + (size_t)brg * 256 + colBase + bcol;
    bool aValid = (rowBase + arow) < M;

    const float4 z4 = make_float4(0.f, 0.f, 0.f, 0.f);
    float4 av0, av1;
    float2 bv0, bv1, bv2, bv3;

    av0 = aValid ? *(const float4*)(Aptr)     : z4;
    av1 = aValid ? *(const float4*)(Aptr + 4) : z4;
    bv0 = *(const float2*)(Bptr);
    bv1 = *(const float2*)(Bptr + 4 * 256);
    bv2 = *(const float2*)(Bptr + 8 * 256);
    bv3 = *(const float2*)(Bptr + 12 * 256);

    {
        float v[8] = {av0.x, av0.y, av0.z, av0.w, av1.x, av1.y, av1.z, av1.w};
        #pragma unroll
        for (int i = 0; i < 4; i++) {
            float2 p;
            *(uint32_t*)&p.x = f2tf32(v[i]);
            *(uint32_t*)&p.y = f2tf32(v[i + 4]);
            As2[0][arow][akc * 4 + i] = p;
        }
        float2 p0, p1, p2, p3;
        *(uint32_t*)&p0.x = f2tf32(bv0.x); *(uint32_t*)&p0.y = f2tf32(bv1.x);
        *(uint32_t*)&p1.x = f2tf32(bv0.y); *(uint32_t*)&p1.y = f2tf32(bv1.y);
        *(uint32_t*)&p2.x = f2tf32(bv2.x); *(uint32_t*)&p2.y = f2tf32(bv3.x);
        *(uint32_t*)&p3.x = f2tf32(bv2.y); *(uint32_t*)&p3.y = f2tf32(bv3.y);
        Bs2[0][brg][bcol]         = p0;
        Bs2[0][brg][bcol + 1]     = p1;
        Bs2[0][brg + 4][bcol]     = p2;
        Bs2[0][brg + 4][bcol + 1] = p3;
    }

    if (tid < 128) {
        sPS[tid][0] = 0.f; sPS[tid][1] = 0.f;
        sPD[tid][0] = 0.f; sPD[tid][1] = 0.f;
    }
    __syncthreads();

    float acc[4][4][4];
    #pragma unroll
    for (int i = 0; i < 4; i++)
        #pragma unroll
        for (int j = 0; j < 4; j++)
            #pragma unroll
            for (int k = 0; k < 4; k++) acc[i][j][k] = 0.f;

    #pragma unroll 1
    for (int kt = 0; kt < 16; kt++) {
        int cur = kt & 1;

        if (kt < 15) {
            const float* Ap = Aptr + (kt + 1) * 16;
            const float* Bp = Bptr + (size_t)(kt + 1) * 16 * 256;
            av0 = aValid ? *(const float4*)(Ap)     : z4;
            av1 = aValid ? *(const float4*)(Ap + 4) : z4;
            bv0 = *(const float2*)(Bp);
            bv1 = *(const float2*)(Bp + 4 * 256);
            bv2 = *(const float2*)(Bp + 8 * 256);
            bv3 = *(const float2*)(Bp + 12 * 256);
        }

        #pragma unroll
        for (int kc = 0; kc < 2; kc++) {
            int kp = kc * 4 + t;
            uint32_t af[4][4], bf[4][2];
            #pragma unroll
            for (int mt = 0; mt < 4; mt++) {
                int m0 = wm * 64 + mt * 16 + g;
                float2 pa0 = As2[cur][m0][kp];
                float2 pa1 = As2[cur][m0 + 8][kp];
                af[mt][0] = *(uint32_t*)&pa0.x;
                af[mt][1] = *(uint32_t*)&pa1.x;
                af[mt][2] = *(uint32_t*)&pa0.y;
                af[mt][3] = *(uint32_t*)&pa1.y;
            }
            #pragma unroll
            for (int nt = 0; nt < 4; nt++) {
                int n0 = wn * 32 + nt * 8 + g;
                float2 pb = Bs2[cur][kp][n0];
                bf[nt][0] = *(uint32_t*)&pb.x;
                bf[nt][1] = *(uint32_t*)&pb.y;
            }
            #pragma unroll
            for (int mt = 0; mt < 4; mt++)
                #pragma unroll
                for (int nt = 0; nt < 4; nt++)
                    mma_tf32(acc[mt][nt], af[mt], bf[nt]);
        }

        if (kt < 15) {
            int nxt = cur ^ 1;
            float v[8] = {av0.x, av0.y, av0.z, av0.w, av1.x, av1.y, av1.z, av1.w};
            #pragma unroll
            for (int i = 0; i < 4; i++) {
                float2 p;
                *(uint32_t*)&p.x = f2tf32(v[i]);
                *(uint32_t*)&p.y = f2tf32(v[i + 4]);
                As2[nxt][arow][akc * 4 + i] = p;
            }
            float2 p0, p1, p2, p3;
            *(uint32_t*)&p0.x = f2tf32(bv0.x); *(uint32_t*)&p0.y = f2tf32(bv1.x);
            *(uint32_t*)&p1.x = f2tf32(bv0.y); *(uint32_t*)&p1.y = f2tf32(bv1.y);
            *(uint32_t*)&p2.x = f2tf32(bv2.x); *(uint32_t*)&p2.y = f2tf32(bv3.x);
            *(uint32_t*)&p3.x = f2tf32(bv2.y); *(uint32_t*)&p3.y = f2tf32(bv3.y);
            Bs2[nxt][brg][bcol]         = p0;
            Bs2[nxt][brg][bcol + 1]     = p1;
            Bs2[nxt][brg + 4][bcol]     = p2;
            Bs2[nxt][brg + 4][bcol + 1] = p3;
            __syncthreads();
        }
    }

    // ---- store C ----
    #pragma unroll
    for (int mt = 0; mt < 4; mt++) {
        int r0 = rowBase + wm * 64 + mt * 16 + g;
        int r1 = r0 + 8;
        #pragma unroll
        for (int nt = 0; nt < 4; nt++) {
            int c = colBase + wn * 32 + nt * 8 + 2 * t;
            if (r0 < M)
                *(float2*)(&C[(size_t)r0 * 256 + c]) = make_float2(acc[mt][nt][0], acc[mt][nt][1]);
            if (r1 < M)
                *(float2*)(&C[(size_t)r1 * 256 + c]) = make_float2(acc[mt][nt][2], acc[mt][nt][3]);
        }
    }

    // ---- fused attention-coefficient epilogue ----
    int hl = wn >> 1;
    float ps[4][2], pd[4][2];
    #pragma unroll
    for (int mt = 0; mt < 4; mt++) {
        ps[mt][0] = 0.f; ps[mt][1] = 0.f;
        pd[mt][0] = 0.f; pd[mt][1] = 0.f;
    }
    #pragma unroll
    for (int nt = 0; nt < 4; nt++) {
        int c = colBase + wn * 32 + nt * 8 + 2 * t;
        float as0 = atts[c], as1 = atts[c + 1];
        float ad0 = attd[c], ad1 = attd[c + 1];
        #pragma unroll
        for (int mt = 0; mt < 4; mt++) {
            ps[mt][0] += acc[mt][nt][0] * as0 + acc[mt][nt][1] * as1;
            ps[mt][1] += acc[mt][nt][2] * as0 + acc[mt][nt][3] * as1;
            pd[mt][0] += acc[mt][nt][0] * ad0 + acc[mt][nt][1] * ad1;
            pd[mt][1] += acc[mt][nt][2] * ad0 + acc[mt][nt][3] * ad1;
        }
    }
    #pragma unroll
    for (int o = 1; o <= 2; o <<= 1) {
        #pragma unroll
        for (int mt = 0; mt < 4; mt++) {
            ps[mt][0] += __shfl_xor_sync(0xffffffffu, ps[mt][0], o);
            ps[mt][1] += __shfl_xor_sync(0xffffffffu, ps[mt][1], o);
            pd[mt][0] += __shfl_xor_sync(0xffffffffu, pd[mt][0], o);
            pd[mt][1] += __shfl_xor_sync(0xffffffffu, pd[mt][1], o);
        }
    }
    if (t == 0) {
        #pragma unroll
        for (int mt = 0; mt < 4; mt++) {
            int rl0 = wm * 64 + mt * 16 + g;
            atomicAdd(&sPS[rl0][hl],     ps[mt][0]);
            atomicAdd(&sPS[rl0 + 8][hl], ps[mt][1]);
            atomicAdd(&sPD[rl0][hl],     pd[mt][0]);
            atomicAdd(&sPD[rl0 + 8][hl], pd[mt][1]);
        }
    }
    __syncthreads();
    if (tid < 128) {
        int r = rowBase + tid;
        if (r < M) {
            int hb = blockIdx.y * 2;
            g_asrc[r * 4 + hb]     = sPS[tid][0];
            g_asrc[r * 4 + hb + 1] = sPS[tid][1];
            g_adst[r * 4 + hb]     = sPD[tid][0];
            g_adst[r * 4 + hb + 1] = sPD[tid][1];
        }
    }
}

// --------------------------- CSR construction ------------------------------
__global__ void k_hist(const void* __restrict__ ei, int E)
{
    int i = blockIdx.x * blockDim.x + threadIdx.x;
    if (i < E) {
        int d = edge_at(ei, E, 1, i, g_is64);
        atomicAdd(&g_deg[d], 1);
    }
}

// warp-shuffle block scan (exclusive), 1024 threads  (R9-proven)
__global__ void k_scan1(int n)
{
    __shared__ int wsum[32];
    int lane = threadIdx.x & 31, wid = threadIdx.x >> 5;
    int gid = blockIdx.x * 1024 + threadIdx.x;
    int v = (gid < n) ? g_deg[gid] : 0;
    int s = v;
    #pragma unroll
    for (int o = 1; o < 32; o <<= 1) {
        int u = __shfl_up_sync(0xffffffffu, s, o);
        if (lane >= o) s += u;
    }
    if (lane == 31) wsum[wid] = s;
    __syncthreads();
    if (wid == 0) {
        int w = wsum[lane];
        int wi = w;
        #pragma unroll
        for (int o = 1; o < 32; o <<= 1) {
            int u = __shfl_up_sync(0xffffffffu, wi, o);
            if (lane >= o) wi += u;
        }
        wsum[lane] = wi - w;   // exclusive warp offsets
        if (lane == 31) g_bsum[blockIdx.x] = wi;  // block total
    }
    __syncthreads();
    if (gid < n) g_off[gid] = (s - v) + wsum[wid];
}

__global__ void k_scan2(int nb)
{
    if (threadIdx.x == 0 && blockIdx.x == 0) {
        int run = 0;
        for (int i = 0; i < nb; i++) {
            int t = g_bsum[i];
            g_bsum[i] = run;
            run += t;
        }
    }
}

__global__ void k_scan3(int n, int tot)
{
    int gid = blockIdx.x * 1024 + threadIdx.x;
    if (gid < n) {
        int v = g_off[gid] + g_bsum[blockIdx.x];
        g_off[gid] = v;
        g_cur[gid] = v;
    }
    if (gid == 0) g_off[n] = tot;
}

__global__ void k_scatter(const void* __restrict__ ei, int E, int N)
{
    int i = blockIdx.x * blockDim.x + threadIdx.x;
    int tot = E + N;
    if (i >= tot) return;
    int s, d;
    if (i < E) {
        int is64 = g_is64;
        s = edge_at(ei, E, 0, i, is64);
        d = edge_at(ei, E, 1, i, is64);
    } else {
        s = d = i - E;
    }
    int pos = atomicAdd(&g_cur[d], 1);
    g_csrc[pos] = s;
}

// ---------------------------------------------------------------------------
// Aggregation: one warp per node, single pass, no max subtraction.
// ---------------------------------------------------------------------------
__global__ void k_aggregate3(const float* __restrict__ feat,
                             const float* __restrict__ bias,
                             float* __restrict__ outp, int N, int mode)
{
    int n = (blockIdx.x * blockDim.x + threadIdx.x) >> 5;
    int lane = threadIdx.x & 31;
    if (n >= N) return;

    int s0 = g_off[n], s1 = g_off[n + 1];
    int myh = lane >> 3;
    float myAd = g_adst[n * 4 + myh];
    int coff = lane * 8;

    float denom = 0.f;
    float4 acc0 = make_float4(0.f, 0.f, 0.f, 0.f);
    float4 acc1 = make_float4(0.f, 0.f, 0.f, 0.f);

    for (int j = s0; j < s1; j++) {
        int src = g_csrc[j];
        float e = g_asrc[src * 4 + myh] + myAd;
        e = (e < 0.f) ? 0.2f * e : e;
        float wt = __expf(e);
        denom += wt;
        const float4* hp = (const float4*)(feat + (size_t)src * FDIM + coff);
        float4 v0 = hp[0], v1 = hp[1];
        acc0.x = fmaf(wt, v0.x, acc0.x); acc0.y = fmaf(wt, v0.y, acc0.y);
        acc0.z = fmaf(wt, v0.z, acc0.z); acc0.w = fmaf(wt, v0.w, acc0.w);
        acc1.x = fmaf(wt, v1.x, acc1.x); acc1.y = fmaf(wt, v1.y, acc1.y);
        acc1.z = fmaf(wt, v1.z, acc1.z); acc1.w = fmaf(wt, v1.w, acc1.w);
    }
    float inv = 1.f / denom;
    acc0.x *= inv; acc0.y *= inv; acc0.z *= inv; acc0.w *= inv;
    acc1.x *= inv; acc1.y *= inv; acc1.z *= inv; acc1.w *= inv;

    if (mode == 1) {
        const float4* bp = (const float4*)(bias + coff);
        float4 b0 = bp[0], b1 = bp[1];
        float o0[8] = {acc0.x + b0.x, acc0.y + b0.y, acc0.z + b0.z, acc0.w + b0.w,
                       acc1.x + b1.x, acc1.y + b1.y, acc1.z + b1.z, acc1.w + b1.w};
        #pragma unroll
        for (int i = 0; i < 8; i++) o0[i] = (o0[i] > 0.f) ? o0[i] : expm1f(o0[i]);
        float* op = outp + (size_t)n * FDIM + coff;
        *(float4*)(op)     = make_float4(o0[0], o0[1], o0[2], o0[3]);
        *(float4*)(op + 4) = make_float4(o0[4], o0[5], o0[6], o0[7]);
    } else {
        float v[8] = {acc0.x, acc0.y, acc0.z, acc0.w, acc1.x, acc1.y, acc1.z, acc1.w};
        #pragma unroll
        for (int o = 8; o <= 16; o <<= 1)
            #pragma unroll
            for (int i = 0; i < 8; i++)
                v[i] += __shfl_xor_sync(0xffffffffu, v[i], o);
        if (lane < 8) {
            int c = lane * 8;
            const float4* bp = (const float4*)(bias + c);
            float4 b0 = bp[0], b1 = bp[1];
            float* op = outp + (size_t)n * 64 + c;
            *(float4*)(op) = make_float4(0.25f * v[0] + b0.x, 0.25f * v[1] + b0.y,
                                         0.25f * v[2] + b0.z, 0.25f * v[3] + b0.w);
            *(float4*)(op + 4) = make_float4(0.25f * v[4] + b1.x, 0.25f * v[5] + b1.y,
                                             0.25f * v[6] + b1.z, 0.25f * v[7] + b1.w);
        }
    }
}

// ---------------------------------------------------------------------------
extern "C" void kernel_launch(void* const* d_in, const int* in_sizes, int n_in,
                              void* d_out, int out_size)
{
    const float* x     = (const float*)d_in[0];
    const void*  ei    = d_in[1];
    const float* W1    = (const float*)d_in[2];
    const float* atts1 = (const float*)d_in[3];
    const float* attd1 = (const float*)d_in[4];
    const float* bias1 = (const float*)d_in[5];
    const float* W2    = (const float*)d_in[6];
    const float* atts2 = (const float*)d_in[7];
    const float* attd2 = (const float*)d_in[8];
    const float* bias2 = (const float*)d_in[9];

    int N = in_sizes[0] / FDIM;      // 50000
    int E = in_sizes[1] / 2;         // 400000
    int tot = E + N;

    void *ph1, *pact, *ph2;
    cudaGetSymbolAddress(&ph1, g_h1);
    cudaGetSymbolAddress(&pact, g_act);
    cudaGetSymbolAddress(&ph2, g_h2);
    float* h1  = (float*)ph1;
    float* act = (float*)pact;
    float* h2  = (float*)ph2;
    float* z   = (float*)d_out;

    int nscan = (N + 1023) / 1024;
    dim3 gemmGrid((N + 127) / 128, 2);
    int aggBlocks = (N * 32 + 255) / 256;

    // --- Layer-1 GEMM first (independent of CSR) ---
    k_gemm_tf32<<<gemmGrid, 256>>>(x, W1, h1, N, atts1, attd1);

    // --- CSR build (R9-proven 3-kernel scan) ---
    k_init<<<(N + 255) / 256, 256>>>((const int*)ei, E, N);
    k_hist<<<(E + 255) / 256, 256>>>(ei, E);
    k_scan1<<<nscan, 1024>>>(N);
    k_scan2<<<1, 32>>>(nscan);
    k_scan3<<<nscan, 1024>>>(N, tot);
    k_scatter<<<(tot + 255) / 256, 256>>>(ei, E, N);

    // --- Layer 1 aggregate ---
    k_aggregate3<<<aggBlocks, 256>>>(h1, bias1, act, N, 1);

    // --- Layer 2 ---
    k_gemm_tf32<<<gemmGrid, 256>>>(act, W2, h2, N, atts2, attd2);
    k_aggregate3<<<aggBlocks, 256>>>(h2, bias2, z, N, 2);
}

// round 15
// speedup vs baseline: 1.4141x; 1.1093x over previous
#include <cuda_runtime.h>
#include <cuda_fp16.h>
#include <cstdint>

// ---------------------------------------------------------------------------
// GAT 2-layer: N=50000, E=400000 (+N self loops), HEADS=4
// tf32 GEMM (R9-proven) writing fp16 feature tables + fused att-coef
// epilogue; fp16-gather single-pass softmax aggregation; R9 3-kernel scan.
// ---------------------------------------------------------------------------

#define NMAX   50000
#define EMAX   400000
#define TOTMAX (NMAX + EMAX)
#define FDIM   256

__device__ __align__(16) __half g_h1[NMAX * FDIM];
__device__ __align__(16) float  g_act[NMAX * FDIM];
__device__ __align__(16) __half g_h2[NMAX * FDIM];
__device__ __align__(16) float g_asrc[NMAX * 4];
__device__ __align__(16) float g_adst[NMAX * 4];
__device__ int   g_deg[NMAX];
__device__ int   g_off[NMAX + 1];
__device__ int   g_cur[NMAX];
__device__ int   g_bsum[64];
__device__ int   g_csrc[TOTMAX];
__device__ int   g_is64;

// ---------------------------------------------------------------------------
__device__ __forceinline__ int edge_at(const void* ei, int E, int which, int i, int is64)
{
    if (is64) {
        const long long* p = (const long long*)ei;
        return (int)p[(size_t)which * E + i];
    } else {
        const int* p = (const int*)ei;
        return p[(size_t)which * E + i];
    }
}

// detect int64-vs-int32 edge dtype AND init degree array (fused)
__global__ void k_init(const int* ei32, int E, int N)
{
    int i = blockIdx.x * blockDim.x + threadIdx.x;
    if (i < N) g_deg[i] = 1;  // self loop
    if (i == 0) {
        int allz = 1;
        int limit = (E < 64) ? E : 64;
        for (int k = 0; k < limit; k++)
            if (ei32[2 * k + 1] != 0) { allz = 0; break; }
        g_is64 = allz;
    }
}

// ---------------------------------------------------------------------------
// TF32 GEMM, 128x128 tile, BK=16 double-buffered, k-pair-packed smem,
// register-staged A and B. C is written as fp16 (feature table for gather).
// Fused attention-coefficient epilogue (fp32 accumulators).
// ---------------------------------------------------------------------------
__device__ __forceinline__ uint32_t f2tf32(float f)
{
    uint32_t r;
    asm("cvt.rna.tf32.f32 %0, %1;" : "=r"(r) : "f"(f));
    return r;
}

__device__ __forceinline__ void mma_tf32(float* d, const uint32_t* a, const uint32_t* b)
{
    asm volatile(
        "mma.sync.aligned.m16n8k8.row.col.f32.tf32.tf32.f32 "
        "{%0,%1,%2,%3}, {%4,%5,%6,%7}, {%8,%9}, {%0,%1,%2,%3};"
        : "+f"(d[0]), "+f"(d[1]), "+f"(d[2]), "+f"(d[3])
        : "r"(a[0]), "r"(a[1]), "r"(a[2]), "r"(a[3]), "r"(b[0]), "r"(b[1]));
}

#define AS2_STRIDE 12    // float2 units
#define BS2_STRIDE 132   // float2 units

__global__ void __launch_bounds__(256, 2)
k_gemm_tf32(const float* __restrict__ A, const float* __restrict__ B,
            __half* __restrict__ C, int M,
            const float* __restrict__ atts, const float* __restrict__ attd)
{
    __shared__ float2 As2[2][128][AS2_STRIDE];
    __shared__ float2 Bs2[2][8][BS2_STRIDE];
    __shared__ float sPS[128][2];
    __shared__ float sPD[128][2];

    int tid  = threadIdx.x;
    int lane = tid & 31, wid = tid >> 5;
    int wm = wid & 1, wn = wid >> 1;
    int g = lane >> 2, t = lane & 3;

    int rowBase = blockIdx.x * 128;
    int colBase = blockIdx.y * 128;

    int arow = tid >> 1;
    int akc  = tid & 1;
    int brg  = tid >> 6;              // 0..3
    int bcol = (tid & 63) * 2;        // 0..126

    const float* Aptr = A + (size_t)(rowBase + arow) * 256 + akc * 8;
    const float* Bptr = B + (size_t)brg * 256 + colBase + bcol;
    bool aValid = (rowBase + arow) < M;

    const float4 z4 = make_float4(0.f, 0.f, 0.f, 0.f);
    float4 av0, av1;
    float2 bv0, bv1, bv2, bv3;

    av0 = aValid ? *(const float4*)(Aptr)     : z4;
    av1 = aValid ? *(const float4*)(Aptr + 4) : z4;
    bv0 = *(const float2*)(Bptr);
    bv1 = *(const float2*)(Bptr + 4 * 256);
    bv2 = *(const float2*)(Bptr + 8 * 256);
    bv3 = *(const float2*)(Bptr + 12 * 256);

    {
        float v[8] = {av0.x, av0.y, av0.z, av0.w, av1.x, av1.y, av1.z, av1.w};
        #pragma unroll
        for (int i = 0; i < 4; i++) {
            float2 p;
            *(uint32_t*)&p.x = f2tf32(v[i]);
            *(uint32_t*)&p.y = f2tf32(v[i + 4]);
            As2[0][arow][akc * 4 + i] = p;
        }
        float2 p0, p1, p2, p3;
        *(uint32_t*)&p0.x = f2tf32(bv0.x); *(uint32_t*)&p0.y = f2tf32(bv1.x);
        *(uint32_t*)&p1.x = f2tf32(bv0.y); *(uint32_t*)&p1.y = f2tf32(bv1.y);
        *(uint32_t*)&p2.x = f2tf32(bv2.x); *(uint32_t*)&p2.y = f2tf32(bv3.x);
        *(uint32_t*)&p3.x = f2tf32(bv2.y); *(uint32_t*)&p3.y = f2tf32(bv3.y);
        Bs2[0][brg][bcol]         = p0;
        Bs2[0][brg][bcol + 1]     = p1;
        Bs2[0][brg + 4][bcol]     = p2;
        Bs2[0][brg + 4][bcol + 1] = p3;
    }

    if (tid < 128) {
        sPS[tid][0] = 0.f; sPS[tid][1] = 0.f;
        sPD[tid][0] = 0.f; sPD[tid][1] = 0.f;
    }
    __syncthreads();

    float acc[4][4][4];
    #pragma unroll
    for (int i = 0; i < 4; i++)
        #pragma unroll
        for (int j = 0; j < 4; j++)
            #pragma unroll
            for (int k = 0; k < 4; k++) acc[i][j][k] = 0.f;

    #pragma unroll 1
    for (int kt = 0; kt < 16; kt++) {
        int cur = kt & 1;

        if (kt < 15) {
            const float* Ap = Aptr + (kt + 1) * 16;
            const float* Bp = Bptr + (size_t)(kt + 1) * 16 * 256;
            av0 = aValid ? *(const float4*)(Ap)     : z4;
            av1 = aValid ? *(const float4*)(Ap + 4) : z4;
            bv0 = *(const float2*)(Bp);
            bv1 = *(const float2*)(Bp + 4 * 256);
            bv2 = *(const float2*)(Bp + 8 * 256);
            bv3 = *(const float2*)(Bp + 12 * 256);
        }

        #pragma unroll
        for (int kc = 0; kc < 2; kc++) {
            int kp = kc * 4 + t;
            uint32_t af[4][4], bf[4][2];
            #pragma unroll
            for (int mt = 0; mt < 4; mt++) {
                int m0 = wm * 64 + mt * 16 + g;
                float2 pa0 = As2[cur][m0][kp];
                float2 pa1 = As2[cur][m0 + 8][kp];
                af[mt][0] = *(uint32_t*)&pa0.x;
                af[mt][1] = *(uint32_t*)&pa1.x;
                af[mt][2] = *(uint32_t*)&pa0.y;
                af[mt][3] = *(uint32_t*)&pa1.y;
            }
            #pragma unroll
            for (int nt = 0; nt < 4; nt++) {
                int n0 = wn * 32 + nt * 8 + g;
                float2 pb = Bs2[cur][kp][n0];
                bf[nt][0] = *(uint32_t*)&pb.x;
                bf[nt][1] = *(uint32_t*)&pb.y;
            }
            #pragma unroll
            for (int mt = 0; mt < 4; mt++)
                #pragma unroll
                for (int nt = 0; nt < 4; nt++)
                    mma_tf32(acc[mt][nt], af[mt], bf[nt]);
        }

        if (kt < 15) {
            int nxt = cur ^ 1;
            float v[8] = {av0.x, av0.y, av0.z, av0.w, av1.x, av1.y, av1.z, av1.w};
            #pragma unroll
            for (int i = 0; i < 4; i++) {
                float2 p;
                *(uint32_t*)&p.x = f2tf32(v[i]);
                *(uint32_t*)&p.y = f2tf32(v[i + 4]);
                As2[nxt][arow][akc * 4 + i] = p;
            }
            float2 p0, p1, p2, p3;
            *(uint32_t*)&p0.x = f2tf32(bv0.x); *(uint32_t*)&p0.y = f2tf32(bv1.x);
            *(uint32_t*)&p1.x = f2tf32(bv0.y); *(uint32_t*)&p1.y = f2tf32(bv1.y);
            *(uint32_t*)&p2.x = f2tf32(bv2.x); *(uint32_t*)&p2.y = f2tf32(bv3.x);
            *(uint32_t*)&p3.x = f2tf32(bv2.y); *(uint32_t*)&p3.y = f2tf32(bv3.y);
            Bs2[nxt][brg][bcol]         = p0;
            Bs2[nxt][brg][bcol + 1]     = p1;
            Bs2[nxt][brg + 4][bcol]     = p2;
            Bs2[nxt][brg + 4][bcol + 1] = p3;
            __syncthreads();
        }
    }

    // ---- store C as fp16 ----
    #pragma unroll
    for (int mt = 0; mt < 4; mt++) {
        int r0 = rowBase + wm * 64 + mt * 16 + g;
        int r1 = r0 + 8;
        #pragma unroll
        for (int nt = 0; nt < 4; nt++) {
            int c = colBase + wn * 32 + nt * 8 + 2 * t;
            if (r0 < M)
                *(__half2*)(&C[(size_t)r0 * 256 + c]) =
                    __floats2half2_rn(acc[mt][nt][0], acc[mt][nt][1]);
            if (r1 < M)
                *(__half2*)(&C[(size_t)r1 * 256 + c]) =
                    __floats2half2_rn(acc[mt][nt][2], acc[mt][nt][3]);
        }
    }

    // ---- fused attention-coefficient epilogue (fp32 accumulators) ----
    int hl = wn >> 1;
    float ps[4][2], pd[4][2];
    #pragma unroll
    for (int mt = 0; mt < 4; mt++) {
        ps[mt][0] = 0.f; ps[mt][1] = 0.f;
        pd[mt][0] = 0.f; pd[mt][1] = 0.f;
    }
    #pragma unroll
    for (int nt = 0; nt < 4; nt++) {
        int c = colBase + wn * 32 + nt * 8 + 2 * t;
        float as0 = atts[c], as1 = atts[c + 1];
        float ad0 = attd[c], ad1 = attd[c + 1];
        #pragma unroll
        for (int mt = 0; mt < 4; mt++) {
            ps[mt][0] += acc[mt][nt][0] * as0 + acc[mt][nt][1] * as1;
            ps[mt][1] += acc[mt][nt][2] * as0 + acc[mt][nt][3] * as1;
            pd[mt][0] += acc[mt][nt][0] * ad0 + acc[mt][nt][1] * ad1;
            pd[mt][1] += acc[mt][nt][2] * ad0 + acc[mt][nt][3] * ad1;
        }
    }
    #pragma unroll
    for (int o = 1; o <= 2; o <<= 1) {
        #pragma unroll
        for (int mt = 0; mt < 4; mt++) {
            ps[mt][0] += __shfl_xor_sync(0xffffffffu, ps[mt][0], o);
            ps[mt][1] += __shfl_xor_sync(0xffffffffu, ps[mt][1], o);
            pd[mt][0] += __shfl_xor_sync(0xffffffffu, pd[mt][0], o);
            pd[mt][1] += __shfl_xor_sync(0xffffffffu, pd[mt][1], o);
        }
    }
    if (t == 0) {
        #pragma unroll
        for (int mt = 0; mt < 4; mt++) {
            int rl0 = wm * 64 + mt * 16 + g;
            atomicAdd(&sPS[rl0][hl],     ps[mt][0]);
            atomicAdd(&sPS[rl0 + 8][hl], ps[mt][1]);
            atomicAdd(&sPD[rl0][hl],     pd[mt][0]);
            atomicAdd(&sPD[rl0 + 8][hl], pd[mt][1]);
        }
    }
    __syncthreads();
    if (tid < 128) {
        int r = rowBase + tid;
        if (r < M) {
            int hb = blockIdx.y * 2;
            g_asrc[r * 4 + hb]     = sPS[tid][0];
            g_asrc[r * 4 + hb + 1] = sPS[tid][1];
            g_adst[r * 4 + hb]     = sPD[tid][0];
            g_adst[r * 4 + hb + 1] = sPD[tid][1];
        }
    }
}

// --------------------------- CSR construction ------------------------------
__global__ void k_hist(const void* __restrict__ ei, int E)
{
    int i = blockIdx.x * blockDim.x + threadIdx.x;
    if (i < E) {
        int d = edge_at(ei, E, 1, i, g_is64);
        atomicAdd(&g_deg[d], 1);
    }
}

__global__ void k_scan1(int n)
{
    __shared__ int wsum[32];
    int lane = threadIdx.x & 31, wid = threadIdx.x >> 5;
    int gid = blockIdx.x * 1024 + threadIdx.x;
    int v = (gid < n) ? g_deg[gid] : 0;
    int s = v;
    #pragma unroll
    for (int o = 1; o < 32; o <<= 1) {
        int u = __shfl_up_sync(0xffffffffu, s, o);
        if (lane >= o) s += u;
    }
    if (lane == 31) wsum[wid] = s;
    __syncthreads();
    if (wid == 0) {
        int w = wsum[lane];
        int wi = w;
        #pragma unroll
        for (int o = 1; o < 32; o <<= 1) {
            int u = __shfl_up_sync(0xffffffffu, wi, o);
            if (lane >= o) wi += u;
        }
        wsum[lane] = wi - w;
        if (lane == 31) g_bsum[blockIdx.x] = wi;
    }
    __syncthreads();
    if (gid < n) g_off[gid] = (s - v) + wsum[wid];
}

__global__ void k_scan2(int nb)
{
    if (threadIdx.x == 0 && blockIdx.x == 0) {
        int run = 0;
        for (int i = 0; i < nb; i++) {
            int t = g_bsum[i];
            g_bsum[i] = run;
            run += t;
        }
    }
}

__global__ void k_scan3(int n, int tot)
{
    int gid = blockIdx.x * 1024 + threadIdx.x;
    if (gid < n) {
        int v = g_off[gid] + g_bsum[blockIdx.x];
        g_off[gid] = v;
        g_cur[gid] = v;
    }
    if (gid == 0) g_off[n] = tot;
}

__global__ void k_scatter(const void* __restrict__ ei, int E, int N)
{
    int i = blockIdx.x * blockDim.x + threadIdx.x;
    int tot = E + N;
    if (i >= tot) return;
    int s, d;
    if (i < E) {
        int is64 = g_is64;
        s = edge_at(ei, E, 0, i, is64);
        d = edge_at(ei, E, 1, i, is64);
    } else {
        s = d = i - E;
    }
    int pos = atomicAdd(&g_cur[d], 1);
    g_csrc[pos] = s;
}

// ---------------------------------------------------------------------------
// Aggregation: one warp per node, single pass, fp16 feature gather.
// Lane L owns 8 contiguous channels (16 bytes) of head (L>>3).
// mode 1: out[n,256] = elu(acc/denom + bias1)   (fp32 out)
// mode 2: out[n,64]  = mean_heads(acc/denom) + bias2
// ---------------------------------------------------------------------------
__global__ void k_aggregate3(const __half* __restrict__ feat,
                             const float* __restrict__ bias,
                             float* __restrict__ outp, int N, int mode)
{
    int n = (blockIdx.x * blockDim.x + threadIdx.x) >> 5;
    int lane = threadIdx.x & 31;
    if (n >= N) return;

    int s0 = g_off[n], s1 = g_off[n + 1];
    int myh = lane >> 3;
    float myAd = g_adst[n * 4 + myh];
    int coff = lane * 8;

    float denom = 0.f;
    float4 acc0 = make_float4(0.f, 0.f, 0.f, 0.f);
    float4 acc1 = make_float4(0.f, 0.f, 0.f, 0.f);

    for (int j = s0; j < s1; j++) {
        int src = g_csrc[j];
        float e = g_asrc[src * 4 + myh] + myAd;
        e = (e < 0.f) ? 0.2f * e : e;
        float wt = __expf(e);
        denom += wt;
        uint4 pv = *(const uint4*)(feat + (size_t)src * FDIM + coff);
        float2 f0 = __half22float2(*(__half2*)&pv.x);
        float2 f1 = __half22float2(*(__half2*)&pv.y);
        float2 f2 = __half22float2(*(__half2*)&pv.z);
        float2 f3 = __half22float2(*(__half2*)&pv.w);
        acc0.x = fmaf(wt, f0.x, acc0.x); acc0.y = fmaf(wt, f0.y, acc0.y);
        acc0.z = fmaf(wt, f1.x, acc0.z); acc0.w = fmaf(wt, f1.y, acc0.w);
        acc1.x = fmaf(wt, f2.x, acc1.x); acc1.y = fmaf(wt, f2.y, acc1.y);
        acc1.z = fmaf(wt, f3.x, acc1.z); acc1.w = fmaf(wt, f3.y, acc1.w);
    }
    float inv = 1.f / denom;
    acc0.x *= inv; acc0.y *= inv; acc0.z *= inv; acc0.w *= inv;
    acc1.x *= inv; acc1.y *= inv; acc1.z *= inv; acc1.w *= inv;

    if (mode == 1) {
        const float4* bp = (const float4*)(bias + coff);
        float4 b0 = bp[0], b1 = bp[1];
        float o0[8] = {acc0.x + b0.x, acc0.y + b0.y, acc0.z + b0.z, acc0.w + b0.w,
                       acc1.x + b1.x, acc1.y + b1.y, acc1.z + b1.z, acc1.w + b1.w};
        #pragma unroll
        for (int i = 0; i < 8; i++) o0[i] = (o0[i] > 0.f) ? o0[i] : expm1f(o0[i]);
        float* op = outp + (size_t)n * FDIM + coff;
        *(float4*)(op)     = make_float4(o0[0], o0[1], o0[2], o0[3]);
        *(float4*)(op + 4) = make_float4(o0[4], o0[5], o0[6], o0[7]);
    } else {
        float v[8] = {acc0.x, acc0.y, acc0.z, acc0.w, acc1.x, acc1.y, acc1.z, acc1.w};
        #pragma unroll
        for (int o = 8; o <= 16; o <<= 1)
            #pragma unroll
            for (int i = 0; i < 8; i++)
                v[i] += __shfl_xor_sync(0xffffffffu, v[i], o);
        if (lane < 8) {
            int c = lane * 8;
            const float4* bp = (const float4*)(bias + c);
            float4 b0 = bp[0], b1 = bp[1];
            float* op = outp + (size_t)n * 64 + c;
            *(float4*)(op) = make_float4(0.25f * v[0] + b0.x, 0.25f * v[1] + b0.y,
                                         0.25f * v[2] + b0.z, 0.25f * v[3] + b0.w);
            *(float4*)(op + 4) = make_float4(0.25f * v[4] + b1.x, 0.25f * v[5] + b1.y,
                                             0.25f * v[6] + b1.z, 0.25f * v[7] + b1.w);
        }
    }
}

// ---------------------------------------------------------------------------
extern "C" void kernel_launch(void* const* d_in, const int* in_sizes, int n_in,
                              void* d_out, int out_size)
{
    const float* x     = (const float*)d_in[0];
    const void*  ei    = d_in[1];
    const float* W1    = (const float*)d_in[2];
    const float* atts1 = (const float*)d_in[3];
    const float* attd1 = (const float*)d_in[4];
    const float* bias1 = (const float*)d_in[5];
    const float* W2    = (const float*)d_in[6];
    const float* atts2 = (const float*)d_in[7];
    const float* attd2 = (const float*)d_in[8];
    const float* bias2 = (const float*)d_in[9];

    int N = in_sizes[0] / FDIM;      // 50000
    int E = in_sizes[1] / 2;         // 400000
    int tot = E + N;

    void *ph1, *pact, *ph2;
    cudaGetSymbolAddress(&ph1, g_h1);
    cudaGetSymbolAddress(&pact, g_act);
    cudaGetSymbolAddress(&ph2, g_h2);
    __half* h1  = (__half*)ph1;
    float*  act = (float*)pact;
    __half* h2  = (__half*)ph2;
    float*  z   = (float*)d_out;

    int nscan = (N + 1023) / 1024;
    dim3 gemmGrid((N + 127) / 128, 2);
    int aggBlocks = (N * 32 + 255) / 256;

    // --- Layer-1 GEMM first (independent of CSR) ---
    k_gemm_tf32<<<gemmGrid, 256>>>(x, W1, h1, N, atts1, attd1);

    // --- CSR build (R9-proven 3-kernel scan) ---
    k_init<<<(N + 255) / 256, 256>>>((const int*)ei, E, N);
    k_hist<<<(E + 255) / 256, 256>>>(ei, E);
    k_scan1<<<nscan, 1024>>>(N);
    k_scan2<<<1, 32>>>(nscan);
    k_scan3<<<nscan, 1024>>>(N, tot);
    k_scatter<<<(tot + 255) / 256, 256>>>(ei, E, N);

    // --- Layer 1 aggregate (fp16 gather -> fp32 act) ---
    k_aggregate3<<<aggBlocks, 256>>>(h1, bias1, act, N, 1);

    // --- Layer 2 ---
    k_gemm_tf32<<<gemmGrid, 256>>>(act, W2, h2, N, atts2, attd2);
    k_aggregate3<<<aggBlocks, 256>>>(h2, bias2, z, N, 2);
}

// round 17
// speedup vs baseline: 1.6247x; 1.1490x over previous
#include <cuda_runtime.h>
#include <cuda_fp16.h>
#include <cstdint>

// ---------------------------------------------------------------------------
// GAT 2-layer: N=50000, E=400000 (+N self loops), HEADS=4
// fp16 MMA (m16n8k16) GEMM writing fp16 feature tables + fused att-coef
// epilogue; fp16-gather single-pass softmax aggregation; R9 3-kernel scan.
// ---------------------------------------------------------------------------

#define NMAX   50000
#define EMAX   400000
#define TOTMAX (NMAX + EMAX)
#define FDIM   256

__device__ __align__(16) __half g_h1[NMAX * FDIM];
__device__ __align__(16) float  g_act[NMAX * FDIM];
__device__ __align__(16) __half g_h2[NMAX * FDIM];
__device__ __align__(16) float g_asrc[NMAX * 4];
__device__ __align__(16) float g_adst[NMAX * 4];
__device__ int   g_deg[NMAX];
__device__ int   g_off[NMAX + 1];
__device__ int   g_cur[NMAX];
__device__ int   g_bsum[64];
__device__ int   g_csrc[TOTMAX];
__device__ int   g_is64;

// ---------------------------------------------------------------------------
__device__ __forceinline__ int edge_at(const void* ei, int E, int which, int i, int is64)
{
    if (is64) {
        const long long* p = (const long long*)ei;
        return (int)p[(size_t)which * E + i];
    } else {
        const int* p = (const int*)ei;
        return p[(size_t)which * E + i];
    }
}

__global__ void k_init(const int* ei32, int E, int N)
{
    int i = blockIdx.x * blockDim.x + threadIdx.x;
    if (i < N) g_deg[i] = 1;  // self loop
    if (i == 0) {
        int allz = 1;
        int limit = (E < 64) ? E : 64;
        for (int k = 0; k < limit; k++)
            if (ei32[2 * k + 1] != 0) { allz = 0; break; }
        g_is64 = allz;
    }
}

// ---------------------------------------------------------------------------
// fp16 GEMM, 128x128 tile, BK=16 double-buffered.
// AsP[m][t] = {h2(A[m][2t],A[m][2t+1]), h2(A[m][2t+8],A[m][2t+9])}   t=0..3
// BsP[t][n] = {h2(B[2t][n],B[2t+1][n]), h2(B[2t+8][n],B[2t+9][n])}
// mma.m16n8k16.f32.f16.f16.f32; fused att-coef epilogue; C stored fp16.
// ---------------------------------------------------------------------------
__device__ __forceinline__ uint32_t pack_h2(float a, float b)
{
    __half2 h = __floats2half2_rn(a, b);
    return *(uint32_t*)&h;
}

__device__ __forceinline__ void mma_f16(float* d, const uint32_t* a, const uint32_t* b)
{
    asm volatile(
        "mma.sync.aligned.m16n8k16.row.col.f32.f16.f16.f32 "
        "{%0,%1,%2,%3}, {%4,%5,%6,%7}, {%8,%9}, {%0,%1,%2,%3};"
        : "+f"(d[0]), "+f"(d[1]), "+f"(d[2]), "+f"(d[3])
        : "r"(a[0]), "r"(a[1]), "r"(a[2]), "r"(a[3]), "r"(b[0]), "r"(b[1]));
}

#define BSP_STRIDE 132   // uint2 units

__global__ void __launch_bounds__(256, 2)
k_gemm_f16(const float* __restrict__ A, const float* __restrict__ B,
           __half* __restrict__ C, int M,
           const float* __restrict__ atts, const float* __restrict__ attd)
{
    __shared__ uint2 AsP[2][128][4];
    __shared__ uint2 BsP[2][4][BSP_STRIDE];
    __shared__ float sPS[128][2];
    __shared__ float sPD[128][2];

    int tid  = threadIdx.x;
    int lane = tid & 31, wid = tid >> 5;
    int wm = wid & 1, wn = wid >> 1;
    int g = lane >> 2, t = lane & 3;

    int rowBase = blockIdx.x * 128;
    int colBase = blockIdx.y * 128;

    // A staging: thread -> (row, 4-col group); loads float4 at 4*akc and 4*akc+8
    int arow = tid >> 1;
    int akc  = tid & 1;
    // B staging: thread -> (t-group, 2 cols); rows 2t,2t+1,2t+8,2t+9
    int bt   = tid >> 6;              // 0..3
    int bcol = (tid & 63) * 2;        // 0..126

    const float* Aptr = A + (size_t)(rowBase + arow) * 256 + akc * 4;
    const float* Bptr = B + (size_t)(2 * bt) * 256 + colBase + bcol;
    bool aValid = (rowBase + arow) < M;

    const float4 z4 = make_float4(0.f, 0.f, 0.f, 0.f);
    float4 av0, av1;
    float2 r0, r1, r2, r3;

    // ---- stage tile 0 ----
    av0 = aValid ? *(const float4*)(Aptr)     : z4;   // cols 4akc..+3
    av1 = aValid ? *(const float4*)(Aptr + 8) : z4;   // cols 4akc+8..+11
    r0 = *(const float2*)(Bptr);
    r1 = *(const float2*)(Bptr + 256);
    r2 = *(const float2*)(Bptr + 8 * 256);
    r3 = *(const float2*)(Bptr + 9 * 256);

    {
        AsP[0][arow][2 * akc]     = make_uint2(pack_h2(av0.x, av0.y), pack_h2(av1.x, av1.y));
        AsP[0][arow][2 * akc + 1] = make_uint2(pack_h2(av0.z, av0.w), pack_h2(av1.z, av1.w));
        BsP[0][bt][bcol]     = make_uint2(pack_h2(r0.x, r1.x), pack_h2(r2.x, r3.x));
        BsP[0][bt][bcol + 1] = make_uint2(pack_h2(r0.y, r1.y), pack_h2(r2.y, r3.y));
    }

    if (tid < 128) {
        sPS[tid][0] = 0.f; sPS[tid][1] = 0.f;
        sPD[tid][0] = 0.f; sPD[tid][1] = 0.f;
    }
    __syncthreads();

    float acc[4][4][4];
    #pragma unroll
    for (int i = 0; i < 4; i++)
        #pragma unroll
        for (int j = 0; j < 4; j++)
            #pragma unroll
            for (int k = 0; k < 4; k++) acc[i][j][k] = 0.f;

    #pragma unroll 1
    for (int kt = 0; kt < 16; kt++) {
        int cur = kt & 1;

        if (kt < 15) {
            const float* Ap = Aptr + (kt + 1) * 16;
            const float* Bp = Bptr + (size_t)(kt + 1) * 16 * 256;
            av0 = aValid ? *(const float4*)(Ap)     : z4;
            av1 = aValid ? *(const float4*)(Ap + 8) : z4;
            r0 = *(const float2*)(Bp);
            r1 = *(const float2*)(Bp + 256);
            r2 = *(const float2*)(Bp + 8 * 256);
            r3 = *(const float2*)(Bp + 9 * 256);
        }

        {
            uint32_t af[4][4], bf[4][2];
            #pragma unroll
            for (int mt = 0; mt < 4; mt++) {
                int m0 = wm * 64 + mt * 16 + g;
                uint2 alo = AsP[cur][m0][t];
                uint2 ahi = AsP[cur][m0 + 8][t];
                af[mt][0] = alo.x;   // A[g][2t,2t+1]
                af[mt][1] = ahi.x;   // A[g+8][2t,2t+1]
                af[mt][2] = alo.y;   // A[g][2t+8,2t+9]
                af[mt][3] = ahi.y;   // A[g+8][2t+8,2t+9]
            }
            #pragma unroll
            for (int nt = 0; nt < 4; nt++) {
                int n0 = wn * 32 + nt * 8 + g;
                uint2 bb = BsP[cur][t][n0];
                bf[nt][0] = bb.x;    // B[2t,2t+1][n]
                bf[nt][1] = bb.y;    // B[2t+8,2t+9][n]
            }
            #pragma unroll
            for (int mt = 0; mt < 4; mt++)
                #pragma unroll
                for (int nt = 0; nt < 4; nt++)
                    mma_f16(acc[mt][nt], af[mt], bf[nt]);
        }

        if (kt < 15) {
            int nxt = cur ^ 1;
            AsP[nxt][arow][2 * akc]     = make_uint2(pack_h2(av0.x, av0.y), pack_h2(av1.x, av1.y));
            AsP[nxt][arow][2 * akc + 1] = make_uint2(pack_h2(av0.z, av0.w), pack_h2(av1.z, av1.w));
            BsP[nxt][bt][bcol]     = make_uint2(pack_h2(r0.x, r1.x), pack_h2(r2.x, r3.x));
            BsP[nxt][bt][bcol + 1] = make_uint2(pack_h2(r0.y, r1.y), pack_h2(r2.y, r3.y));
            __syncthreads();
        }
    }

    // ---- store C as fp16 ----
    #pragma unroll
    for (int mt = 0; mt < 4; mt++) {
        int r0r = rowBase + wm * 64 + mt * 16 + g;
        int r1r = r0r + 8;
        #pragma unroll
        for (int nt = 0; nt < 4; nt++) {
            int c = colBase + wn * 32 + nt * 8 + 2 * t;
            if (r0r < M)
                *(__half2*)(&C[(size_t)r0r * 256 + c]) =
                    __floats2half2_rn(acc[mt][nt][0], acc[mt][nt][1]);
            if (r1r < M)
                *(__half2*)(&C[(size_t)r1r * 256 + c]) =
                    __floats2half2_rn(acc[mt][nt][2], acc[mt][nt][3]);
        }
    }

    // ---- fused attention-coefficient epilogue (fp32 accumulators) ----
    int hl = wn >> 1;
    float ps[4][2], pd[4][2];
    #pragma unroll
    for (int mt = 0; mt < 4; mt++) {
        ps[mt][0] = 0.f; ps[mt][1] = 0.f;
        pd[mt][0] = 0.f; pd[mt][1] = 0.f;
    }
    #pragma unroll
    for (int nt = 0; nt < 4; nt++) {
        int c = colBase + wn * 32 + nt * 8 + 2 * t;
        float as0 = atts[c], as1 = atts[c + 1];
        float ad0 = attd[c], ad1 = attd[c + 1];
        #pragma unroll
        for (int mt = 0; mt < 4; mt++) {
            ps[mt][0] += acc[mt][nt][0] * as0 + acc[mt][nt][1] * as1;
            ps[mt][1] += acc[mt][nt][2] * as0 + acc[mt][nt][3] * as1;
            pd[mt][0] += acc[mt][nt][0] * ad0 + acc[mt][nt][1] * ad1;
            pd[mt][1] += acc[mt][nt][2] * ad0 + acc[mt][nt][3] * ad1;
        }
    }
    #pragma unroll
    for (int o = 1; o <= 2; o <<= 1) {
        #pragma unroll
        for (int mt = 0; mt < 4; mt++) {
            ps[mt][0] += __shfl_xor_sync(0xffffffffu, ps[mt][0], o);
            ps[mt][1] += __shfl_xor_sync(0xffffffffu, ps[mt][1], o);
            pd[mt][0] += __shfl_xor_sync(0xffffffffu, pd[mt][0], o);
            pd[mt][1] += __shfl_xor_sync(0xffffffffu, pd[mt][1], o);
        }
    }
    if (t == 0) {
        #pragma unroll
        for (int mt = 0; mt < 4; mt++) {
            int rl0 = wm * 64 + mt * 16 + g;
            atomicAdd(&sPS[rl0][hl],     ps[mt][0]);
            atomicAdd(&sPS[rl0 + 8][hl], ps[mt][1]);
            atomicAdd(&sPD[rl0][hl],     pd[mt][0]);
            atomicAdd(&sPD[rl0 + 8][hl], pd[mt][1]);
        }
    }
    __syncthreads();
    if (tid < 128) {
        int r = rowBase + tid;
        if (r < M) {
            int hb = blockIdx.y * 2;
            g_asrc[r * 4 + hb]     = sPS[tid][0];
            g_asrc[r * 4 + hb + 1] = sPS[tid][1];
            g_adst[r * 4 + hb]     = sPD[tid][0];
            g_adst[r * 4 + hb + 1] = sPD[tid][1];
        }
    }
}

// --------------------------- CSR construction ------------------------------
__global__ void k_hist(const void* __restrict__ ei, int E)
{
    int i = blockIdx.x * blockDim.x + threadIdx.x;
    if (i < E) {
        int d = edge_at(ei, E, 1, i, g_is64);
        atomicAdd(&g_deg[d], 1);
    }
}

__global__ void k_scan1(int n)
{
    __shared__ int wsum[32];
    int lane = threadIdx.x & 31, wid = threadIdx.x >> 5;
    int gid = blockIdx.x * 1024 + threadIdx.x;
    int v = (gid < n) ? g_deg[gid] : 0;
    int s = v;
    #pragma unroll
    for (int o = 1; o < 32; o <<= 1) {
        int u = __shfl_up_sync(0xffffffffu, s, o);
        if (lane >= o) s += u;
    }
    if (lane == 31) wsum[wid] = s;
    __syncthreads();
    if (wid == 0) {
        int w = wsum[lane];
        int wi = w;
        #pragma unroll
        for (int o = 1; o < 32; o <<= 1) {
            int u = __shfl_up_sync(0xffffffffu, wi, o);
            if (lane >= o) wi += u;
        }
        wsum[lane] = wi - w;
        if (lane == 31) g_bsum[blockIdx.x] = wi;
    }
    __syncthreads();
    if (gid < n) g_off[gid] = (s - v) + wsum[wid];
}

__global__ void k_scan2(int nb)
{
    if (threadIdx.x == 0 && blockIdx.x == 0) {
        int run = 0;
        for (int i = 0; i < nb; i++) {
            int t = g_bsum[i];
            g_bsum[i] = run;
            run += t;
        }
    }
}

__global__ void k_scan3(int n, int tot)
{
    int gid = blockIdx.x * 1024 + threadIdx.x;
    if (gid < n) {
        int v = g_off[gid] + g_bsum[blockIdx.x];
        g_off[gid] = v;
        g_cur[gid] = v;
    }
    if (gid == 0) g_off[n] = tot;
}

__global__ void k_scatter(const void* __restrict__ ei, int E, int N)
{
    int i = blockIdx.x * blockDim.x + threadIdx.x;
    int tot = E + N;
    if (i >= tot) return;
    int s, d;
    if (i < E) {
        int is64 = g_is64;
        s = edge_at(ei, E, 0, i, is64);
        d = edge_at(ei, E, 1, i, is64);
    } else {
        s = d = i - E;
    }
    int pos = atomicAdd(&g_cur[d], 1);
    g_csrc[pos] = s;
}

// ---------------------------------------------------------------------------
// Aggregation: one warp per node, single pass, fp16 feature gather.
// ---------------------------------------------------------------------------
__global__ void k_aggregate3(const __half* __restrict__ feat,
                             const float* __restrict__ bias,
                             float* __restrict__ outp, int N, int mode)
{
    int n = (blockIdx.x * blockDim.x + threadIdx.x) >> 5;
    int lane = threadIdx.x & 31;
    if (n >= N) return;

    int s0 = g_off[n], s1 = g_off[n + 1];
    int myh = lane >> 3;
    float myAd = g_adst[n * 4 + myh];
    int coff = lane * 8;

    float denom = 0.f;
    float4 acc0 = make_float4(0.f, 0.f, 0.f, 0.f);
    float4 acc1 = make_float4(0.f, 0.f, 0.f, 0.f);

    for (int j = s0; j < s1; j++) {
        int src = g_csrc[j];
        float e = g_asrc[src * 4 + myh] + myAd;
        e = (e < 0.f) ? 0.2f * e : e;
        float wt = __expf(e);
        denom += wt;
        uint4 pv = *(const uint4*)(feat + (size_t)src * FDIM + coff);
        float2 f0 = __half22float2(*(__half2*)&pv.x);
        float2 f1 = __half22float2(*(__half2*)&pv.y);
        float2 f2 = __half22float2(*(__half2*)&pv.z);
        float2 f3 = __half22float2(*(__half2*)&pv.w);
        acc0.x = fmaf(wt, f0.x, acc0.x); acc0.y = fmaf(wt, f0.y, acc0.y);
        acc0.z = fmaf(wt, f1.x, acc0.z); acc0.w = fmaf(wt, f1.y, acc0.w);
        acc1.x = fmaf(wt, f2.x, acc1.x); acc1.y = fmaf(wt, f2.y, acc1.y);
        acc1.z = fmaf(wt, f3.x, acc1.z); acc1.w = fmaf(wt, f3.y, acc1.w);
    }
    float inv = 1.f / denom;
    acc0.x *= inv; acc0.y *= inv; acc0.z *= inv; acc0.w *= inv;
    acc1.x *= inv; acc1.y *= inv; acc1.z *= inv; acc1.w *= inv;

    if (mode == 1) {
        const float4* bp = (const float4*)(bias + coff);
        float4 b0 = bp[0], b1 = bp[1];
        float o0[8] = {acc0.x + b0.x, acc0.y + b0.y, acc0.z + b0.z, acc0.w + b0.w,
                       acc1.x + b1.x, acc1.y + b1.y, acc1.z + b1.z, acc1.w + b1.w};
        #pragma unroll
        for (int i = 0; i < 8; i++) o0[i] = (o0[i] > 0.f) ? o0[i] : expm1f(o0[i]);
        float* op = outp + (size_t)n * FDIM + coff;
        *(float4*)(op)     = make_float4(o0[0], o0[1], o0[2], o0[3]);
        *(float4*)(op + 4) = make_float4(o0[4], o0[5], o0[6], o0[7]);
    } else {
        float v[8] = {acc0.x, acc0.y, acc0.z, acc0.w, acc1.x, acc1.y, acc1.z, acc1.w};
        #pragma unroll
        for (int o = 8; o <= 16; o <<= 1)
            #pragma unroll
            for (int i = 0; i < 8; i++)
                v[i] += __shfl_xor_sync(0xffffffffu, v[i], o);
        if (lane < 8) {
            int c = lane * 8;
            const float4* bp = (const float4*)(bias + c);
            float4 b0 = bp[0], b1 = bp[1];
            float* op = outp + (size_t)n * 64 + c;
            *(float4*)(op) = make_float4(0.25f * v[0] + b0.x, 0.25f * v[1] + b0.y,
                                         0.25f * v[2] + b0.z, 0.25f * v[3] + b0.w);
            *(float4*)(op + 4) = make_float4(0.25f * v[4] + b1.x, 0.25f * v[5] + b1.y,
                                             0.25f * v[6] + b1.z, 0.25f * v[7] + b1.w);
        }
    }
}

// ---------------------------------------------------------------------------
extern "C" void kernel_launch(void* const* d_in, const int* in_sizes, int n_in,
                              void* d_out, int out_size)
{
    const float* x     = (const float*)d_in[0];
    const void*  ei    = d_in[1];
    const float* W1    = (const float*)d_in[2];
    const float* atts1 = (const float*)d_in[3];
    const float* attd1 = (const float*)d_in[4];
    const float* bias1 = (const float*)d_in[5];
    const float* W2    = (const float*)d_in[6];
    const float* atts2 = (const float*)d_in[7];
    const float* attd2 = (const float*)d_in[8];
    const float* bias2 = (const float*)d_in[9];

    int N = in_sizes[0] / FDIM;      // 50000
    int E = in_sizes[1] / 2;         // 400000
    int tot = E + N;

    void *ph1, *pact, *ph2;
    cudaGetSymbolAddress(&ph1, g_h1);
    cudaGetSymbolAddress(&pact, g_act);
    cudaGetSymbolAddress(&ph2, g_h2);
    __half* h1  = (__half*)ph1;
    float*  act = (float*)pact;
    __half* h2  = (__half*)ph2;
    float*  z   = (float*)d_out;

    int nscan = (N + 1023) / 1024;
    dim3 gemmGrid((N + 127) / 128, 2);
    int aggBlocks = (N * 32 + 255) / 256;

    // --- Layer-1 GEMM first (independent of CSR) ---
    k_gemm_f16<<<gemmGrid, 256>>>(x, W1, h1, N, atts1, attd1);

    // --- CSR build (R9-proven 3-kernel scan) ---
    k_init<<<(N + 255) / 256, 256>>>((const int*)ei, E, N);
    k_hist<<<(E + 255) / 256, 256>>>(ei, E);
    k_scan1<<<nscan, 1024>>>(N);
    k_scan2<<<1, 32>>>(nscan);
    k_scan3<<<nscan, 1024>>>(N, tot);
    k_scatter<<<(tot + 255) / 256, 256>>>(ei, E, N);

    // --- Layer 1 aggregate (fp16 gather -> fp32 act) ---
    k_aggregate3<<<aggBlocks, 256>>>(h1, bias1, act, N, 1);

    // --- Layer 2 ---
    k_gemm_f16<<<gemmGrid, 256>>>(act, W2, h2, N, atts2, attd2);
    k_aggregate3<<<aggBlocks, 256>>>(h2, bias2, z, N, 2);
}